// round 16
// baseline (speedup 1.0000x reference)
#include <cuda_runtime.h>
#include <cstdint>
#include <cstddef>

// ---------------------------------------------------------------------------
// MultiModalClinicalGCN
//   m  = relu(mel @ W_mel + b_mel)                      [N,128]
//   x1 = relu([clinical | m] @ W_cat + b_cat)           [N,192]->[N,128]
//   x2 = relu(gcn(x1, W1, b1))                          [N,128]
//   out= gcn(x2, W2, b2)                                [N,4]
// gcn(x,W,b): h=xW; out[i]=dinv[i]*(sum_{e:dst=i} dinv[src]h[src] + dinv[i]h[i]) + b
// deg[i] = indegree(i) + 1 (self loop), dinv = rsqrt(deg)
//
// KEY FIX vs rounds 11-14: edge_index is int32, NOT int64. JAX with default
// config silently downcasts jnp.int64 randint to int32; reading it as
// long long ran 2x past the buffer -> the illegal memory access seen in every
// failing round. All derived indices remain bounds-guarded, so if the dtype
// assumption is ever wrong we get a numeric failure, not a fault.
//
// Aggregation: build CSR (bucket src ids by dst) once per launch, then GATHER
// per node — zero float atomics.
// ---------------------------------------------------------------------------

#define NMAX 100000
#define EMAX 1600000
#define TB 256
#define NB_MAX 512   // scan level-2 width (NMAX/256 = 391 blocks <= 512)

// float4-typed so all vector accesses are 16B aligned by construction.
__device__ float4 g_m   [(size_t)NMAX * 32];
__device__ float4 g_x1  [(size_t)NMAX * 32];
__device__ float4 g_p1  [(size_t)NMAX * 32];   // dinv[i]*h1[i]
__device__ float4 g_x2  [(size_t)NMAX * 32];
__device__ float4 g_p2  [NMAX];                // dinv[i]*h2[i]
__device__ float  g_dinv[NMAX];
__device__ int    g_cnt [NMAX];
__device__ int    g_off [NMAX + 1];
__device__ int    g_cur [NMAX];
__device__ int    g_bsum[NB_MAX];
__device__ int    g_boff[NB_MAX];
__device__ int    g_eidx[EMAX];                // src ids bucketed by dst

// ---------------- degree histogram ------------------------------------------
__global__ void k_zerocnt(int* cnt, int n) {
    int i = blockIdx.x * blockDim.x + threadIdx.x;
    if (i < n) cnt[i] = 0;
}

__global__ void k_hist(const int* __restrict__ dst, int* cnt, int n, int e) {
    int i = blockIdx.x * blockDim.x + threadIdx.x;
    if (i >= e) return;
    unsigned d = (unsigned)dst[i];
    if (d < (unsigned)n) atomicAdd(&cnt[d], 1);
}

// ---------------- hierarchical exclusive scan --------------------------------
// Level 1: per-block (256-wide) Hillis-Steele; local exclusive prefix to off,
// block total to bsum. Fused dinv = rsqrt(cnt+1).
__global__ void k_scan1(const int* __restrict__ cnt, int* __restrict__ off,
                        int* __restrict__ bsum, float* __restrict__ dinv, int n) {
    __shared__ int sh[TB];
    int tid = threadIdx.x;
    int i = blockIdx.x * TB + tid;
    int v = (i < n) ? cnt[i] : 0;
    if (i < n) dinv[i] = rsqrtf((float)v + 1.0f);   // +1 self loop
    sh[tid] = v;
    __syncthreads();
#pragma unroll
    for (int d = 1; d < TB; d <<= 1) {
        int t = (tid >= d) ? sh[tid - d] : 0;
        __syncthreads();
        sh[tid] += t;
        __syncthreads();
    }
    if (i < n) off[i] = sh[tid] - v;                // exclusive
    if (tid == TB - 1) bsum[blockIdx.x] = sh[TB - 1];
}

// Level 2: single block scans the <=NB_MAX block sums (exclusive).
__global__ void k_scan2(const int* __restrict__ bsum, int* __restrict__ boff, int nb) {
    __shared__ int sh[NB_MAX];
    int tid = threadIdx.x;
    int v = (tid < nb) ? bsum[tid] : 0;
    sh[tid] = v;
    __syncthreads();
#pragma unroll
    for (int d = 1; d < NB_MAX; d <<= 1) {
        int t = (tid >= d) ? sh[tid - d] : 0;
        __syncthreads();
        sh[tid] += t;
        __syncthreads();
    }
    if (tid < nb) boff[tid] = sh[tid] - v;          // exclusive
}

// Level 3: add block prefix; emit off[n]; init cur = off.
__global__ void k_scan3(const int* __restrict__ cnt, const int* __restrict__ boff,
                        int* __restrict__ off, int* __restrict__ cur, int n) {
    int i = blockIdx.x * blockDim.x + threadIdx.x;
    if (i >= n) return;
    int o = off[i] + boff[i >> 8];
    off[i] = o;
    cur[i] = o;
    if (i == n - 1) off[n] = o + cnt[i];
}

// ---------------- bucket edges by dst ----------------------------------------
__global__ void k_bucket(const int* __restrict__ src,
                         const int* __restrict__ dst,
                         int* cur, int* __restrict__ eidx, int n, int e) {
    int i = blockIdx.x * blockDim.x + threadIdx.x;
    if (i >= e) return;
    unsigned d = (unsigned)dst[i];
    if (d >= (unsigned)n) return;                    // defensive
    int p = atomicAdd(&cur[d], 1);
    if ((unsigned)p < (unsigned)e)                   // defensive
        eidx[p] = src[i];
}

// ---------------- tiled SGEMM, N fixed at 128 -------------------------------
// C[M,128] = A[M,K] * B[K,128]; A virtually = [A1 (cols<split) | A2 (cols>=split)]
// EPI==0: C = relu(acc + bias[col]);  EPI==1: C = dinv[row] * acc
// Block tile 128x128, BK=16, 256 threads, warp tile 32x64, thread tile 8x8.
template <int EPI>
__global__ __launch_bounds__(256)
void k_sgemm(const float* __restrict__ A1, int lda1,
             const float* __restrict__ A2, int lda2, int split,
             const float* __restrict__ B,
             const float* __restrict__ bias,
             const float* __restrict__ dinv,
             float* __restrict__ C, int M, int K) {
    __shared__ float As[16][132];   // [k][m], padded
    __shared__ float Bs[16][128];   // [k][n]

    const int tid  = threadIdx.x;
    const int lane = tid & 31;
    const int ww   = tid >> 5;
    const int wr = ww & 3, wc = ww >> 2;        // warp grid 4x2
    const int tr = lane >> 3, tc = lane & 7;    // lane grid 4x8
    const int rowOff = wr * 32 + tr * 8;
    const int colOff = wc * 64 + tc * 8;
    const int rowBase = blockIdx.x * 128;

    float acc[8][8];
#pragma unroll
    for (int i = 0; i < 8; i++)
#pragma unroll
        for (int j = 0; j < 8; j++) acc[i][j] = 0.f;

    for (int k0 = 0; k0 < K; k0 += 16) {
        // --- A tile: 128 rows x 16 cols, transposed into As[k][m]
        const float* Ap; int lda, kcol;
        if (k0 < split) { Ap = A1; lda = lda1; kcol = k0; }
        else            { Ap = A2; lda = lda2; kcol = k0 - split; }
#pragma unroll
        for (int it = 0; it < 2; it++) {
            int idx = tid + it * 256;          // 0..511
            int r   = idx >> 2;                // 0..127
            int c4  = (idx & 3) * 4;           // 0,4,8,12
            int grow = rowBase + r;
            float4 v = make_float4(0.f, 0.f, 0.f, 0.f);
            if (grow < M)
                v = *reinterpret_cast<const float4*>(Ap + (size_t)grow * lda + kcol + c4);
            As[c4 + 0][r] = v.x; As[c4 + 1][r] = v.y;
            As[c4 + 2][r] = v.z; As[c4 + 3][r] = v.w;
        }
        // --- B tile: 16 x 128
#pragma unroll
        for (int it = 0; it < 2; it++) {
            int idx = tid + it * 256;
            int kr  = idx >> 5;                // 0..15
            int c4  = (idx & 31) * 4;          // 0..124
            *reinterpret_cast<float4*>(&Bs[kr][c4]) =
                *reinterpret_cast<const float4*>(B + (size_t)(k0 + kr) * 128 + c4);
        }
        __syncthreads();

#pragma unroll
        for (int k = 0; k < 16; k++) {
            float a[8], b[8];
            *reinterpret_cast<float4*>(&a[0]) = *reinterpret_cast<const float4*>(&As[k][rowOff]);
            *reinterpret_cast<float4*>(&a[4]) = *reinterpret_cast<const float4*>(&As[k][rowOff + 4]);
            *reinterpret_cast<float4*>(&b[0]) = *reinterpret_cast<const float4*>(&Bs[k][colOff]);
            *reinterpret_cast<float4*>(&b[4]) = *reinterpret_cast<const float4*>(&Bs[k][colOff + 4]);
#pragma unroll
            for (int i = 0; i < 8; i++)
#pragma unroll
                for (int j = 0; j < 8; j++)
                    acc[i][j] = fmaf(a[i], b[j], acc[i][j]);
        }
        __syncthreads();
    }

#pragma unroll
    for (int i = 0; i < 8; i++) {
        int grow = rowBase + rowOff + i;
        if (grow >= M) continue;
        float scale = 1.f;
        if (EPI == 1) scale = dinv[grow];
#pragma unroll
        for (int j = 0; j < 8; j += 4) {
            int col = colOff + j;
            float4 v = make_float4(acc[i][j], acc[i][j + 1], acc[i][j + 2], acc[i][j + 3]);
            if (EPI == 0) {
                v.x = fmaxf(v.x + bias[col + 0], 0.f);
                v.y = fmaxf(v.y + bias[col + 1], 0.f);
                v.z = fmaxf(v.z + bias[col + 2], 0.f);
                v.w = fmaxf(v.w + bias[col + 3], 0.f);
            } else {
                v.x *= scale; v.y *= scale; v.z *= scale; v.w *= scale;
            }
            *reinterpret_cast<float4*>(C + (size_t)grow * 128 + col) = v;
        }
    }
}

// ---------------- conv1: warp-per-node gather + fused relu combine ----------
// x2[i] = relu(dinv[i] * (p1[i] + sum_{e in bucket(i)} p1[src_e]) + b1)
__global__ void k_gather1(const int* __restrict__ off,
                          const int* __restrict__ eidx,
                          const float4* __restrict__ p1,
                          const float* __restrict__ dinv,
                          const float* __restrict__ b1,
                          float4* __restrict__ x2, int n, int e) {
    int node = (blockIdx.x * blockDim.x + threadIdx.x) >> 5;
    if (node >= n) return;
    int lane = threadIdx.x & 31;
    int beg = off[node], end = off[node + 1];
    beg = min(max(beg, 0), e);                       // defensive clamp
    end = min(max(end, beg), e);

    // self-loop term: p1[node] already = dinv[node]*h[node]
    float4 acc = p1[(size_t)node * 32 + lane];

    for (int t = beg; t < end; t++) {
        unsigned s = (unsigned)eidx[t];
        if (s >= (unsigned)n) continue;              // defensive
        float4 v = __ldg(p1 + (size_t)s * 32 + lane);
        acc.x += v.x; acc.y += v.y; acc.z += v.z; acc.w += v.w;
    }

    float s = dinv[node];
    float4 bb = *reinterpret_cast<const float4*>(b1 + lane * 4);
    float4 r;
    r.x = fmaxf(fmaf(s, acc.x, bb.x), 0.f);
    r.y = fmaxf(fmaf(s, acc.y, bb.y), 0.f);
    r.z = fmaxf(fmaf(s, acc.z, bb.z), 0.f);
    r.w = fmaxf(fmaf(s, acc.w, bb.w), 0.f);
    x2[(size_t)node * 32 + lane] = r;
}

// ---------------- p2 = dinv * (x2 @ W2[128,4]), one warp per node -----------
__global__ void k_gemm4(const float4* __restrict__ x2,
                        const float* __restrict__ W2,
                        const float* __restrict__ dinv,
                        float4* __restrict__ p2, int n) {
    int gw = (blockIdx.x * blockDim.x + threadIdx.x) >> 5;
    if (gw >= n) return;
    int lane = threadIdx.x & 31;
    float4 x = x2[(size_t)gw * 32 + lane];
    const float4* W = reinterpret_cast<const float4*>(W2) + lane * 4;  // rows lane*4..+3
    float4 w0 = W[0], w1 = W[1], w2 = W[2], w3 = W[3];
    float4 acc;
    acc.x = x.x * w0.x + x.y * w1.x + x.z * w2.x + x.w * w3.x;
    acc.y = x.x * w0.y + x.y * w1.y + x.z * w2.y + x.w * w3.y;
    acc.z = x.x * w0.z + x.y * w1.z + x.z * w2.z + x.w * w3.z;
    acc.w = x.x * w0.w + x.y * w1.w + x.z * w2.w + x.w * w3.w;
#pragma unroll
    for (int o = 16; o > 0; o >>= 1) {
        acc.x += __shfl_xor_sync(0xffffffffu, acc.x, o);
        acc.y += __shfl_xor_sync(0xffffffffu, acc.y, o);
        acc.z += __shfl_xor_sync(0xffffffffu, acc.z, o);
        acc.w += __shfl_xor_sync(0xffffffffu, acc.w, o);
    }
    if (lane == 0) {
        float s = dinv[gw];
        p2[gw] = make_float4(s * acc.x, s * acc.y, s * acc.z, s * acc.w);
    }
}

// ---------------- conv2: warp-per-node lane-strided gather ------------------
// out[i] = dinv[i]*(p2[i] + sum p2[src_e]) + b2
__global__ void k_gather2(const int* __restrict__ off,
                          const int* __restrict__ eidx,
                          const float4* __restrict__ p2,
                          const float* __restrict__ dinv,
                          const float* __restrict__ b2,
                          float4* __restrict__ out, int n, int e) {
    int node = (blockIdx.x * blockDim.x + threadIdx.x) >> 5;
    if (node >= n) return;
    int lane = threadIdx.x & 31;
    int beg = off[node], end = off[node + 1];
    beg = min(max(beg, 0), e);
    end = min(max(end, beg), e);

    float4 acc = make_float4(0.f, 0.f, 0.f, 0.f);
    for (int t = beg + lane; t < end; t += 32) {
        unsigned s = (unsigned)eidx[t];
        if (s >= (unsigned)n) continue;              // defensive
        float4 v = __ldg(p2 + s);
        acc.x += v.x; acc.y += v.y; acc.z += v.z; acc.w += v.w;
    }
#pragma unroll
    for (int o = 16; o > 0; o >>= 1) {
        acc.x += __shfl_xor_sync(0xffffffffu, acc.x, o);
        acc.y += __shfl_xor_sync(0xffffffffu, acc.y, o);
        acc.z += __shfl_xor_sync(0xffffffffu, acc.z, o);
        acc.w += __shfl_xor_sync(0xffffffffu, acc.w, o);
    }
    if (lane == 0) {
        float s  = dinv[node];
        float4 p = p2[node];
        float4 b = *reinterpret_cast<const float4*>(b2);
        float4 o;
        o.x = fmaf(s, acc.x + p.x, b.x);
        o.y = fmaf(s, acc.y + p.y, b.y);
        o.z = fmaf(s, acc.z + p.z, b.z);
        o.w = fmaf(s, acc.w + p.w, b.w);
        out[node] = o;
    }
}

// ---------------------------------------------------------------------------
extern "C" void kernel_launch(void* const* d_in, const int* in_sizes, int n_in,
                              void* d_out, int out_size) {
    const float* clinical = (const float*)d_in[0];
    const float* mel      = (const float*)d_in[1];
    const int*   ei       = (const int*)d_in[2];     // int32! (JAX x64 disabled)
    const float* W_mel    = (const float*)d_in[3];
    const float* b_mel    = (const float*)d_in[4];
    const float* W_cat    = (const float*)d_in[5];
    const float* b_cat    = (const float*)d_in[6];
    const float* W1       = (const float*)d_in[7];
    const float* b1       = (const float*)d_in[8];
    const float* W2       = (const float*)d_in[9];
    const float* b2       = (const float*)d_in[10];

    int n = in_sizes[0] / 64;        // 100000
    int e = in_sizes[2] / 2;         // 1600000
    if (n > NMAX) n = NMAX;
    if (e > EMAX) e = EMAX;
    const int* src = ei;
    const int* dst = ei + e;

    float4 *pm, *px1, *pp1, *px2, *pp2;
    float  *pdinv;
    int    *pcnt, *poff, *pcur, *peidx, *pbsum, *pboff;
    cudaGetSymbolAddress((void**)&pm,    g_m);
    cudaGetSymbolAddress((void**)&px1,   g_x1);
    cudaGetSymbolAddress((void**)&pp1,   g_p1);
    cudaGetSymbolAddress((void**)&px2,   g_x2);
    cudaGetSymbolAddress((void**)&pp2,   g_p2);
    cudaGetSymbolAddress((void**)&pdinv, g_dinv);
    cudaGetSymbolAddress((void**)&pcnt,  g_cnt);
    cudaGetSymbolAddress((void**)&poff,  g_off);
    cudaGetSymbolAddress((void**)&pcur,  g_cur);
    cudaGetSymbolAddress((void**)&peidx, g_eidx);
    cudaGetSymbolAddress((void**)&pbsum, g_bsum);
    cudaGetSymbolAddress((void**)&pboff, g_boff);

    int gn = (n + TB - 1) / TB;      // 391 blocks (<= NB_MAX)
    int ge = (e + TB - 1) / TB;

    // --- CSR build (bucket edges by dst) + dinv
    k_zerocnt<<<gn, TB>>>(pcnt, n);
    k_hist<<<ge, TB>>>(dst, pcnt, n, e);
    k_scan1<<<gn, TB>>>(pcnt, poff, pbsum, pdinv, n);
    k_scan2<<<1, NB_MAX>>>(pbsum, pboff, gn);
    k_scan3<<<gn, TB>>>(pcnt, pboff, poff, pcur, n);
    k_bucket<<<ge, TB>>>(src, dst, pcur, peidx, n, e);

    // --- dense pipeline
    int gm = (n + 127) / 128;
    // m = relu(mel @ W_mel + b_mel)
    k_sgemm<0><<<gm, 256>>>(mel, 1024, nullptr, 0, 1 << 30,
                            W_mel, b_mel, nullptr, (float*)pm, n, 1024);
    // x1 = relu([clinical | m] @ W_cat + b_cat)   (virtual concat, split=64)
    k_sgemm<0><<<gm, 256>>>(clinical, 64, (const float*)pm, 128, 64,
                            W_cat, b_cat, nullptr, (float*)px1, n, 192);
    // p1 = dinv * (x1 @ W1)
    k_sgemm<1><<<gm, 256>>>((const float*)px1, 128, nullptr, 0, 1 << 30,
                            W1, nullptr, pdinv, (float*)pp1, n, 128);

    // conv1 gather + fused relu combine -> x2
    int gw = (n * 32 + TB - 1) / TB;   // one warp per node
    k_gather1<<<gw, TB>>>(poff, peidx, pp1, pdinv, b1, px2, n, e);

    // p2 = dinv * (x2 @ W2)
    k_gemm4<<<gw, TB>>>(px2, W2, pdinv, pp2, n);

    // conv2 gather -> out
    k_gather2<<<gw, TB>>>(poff, peidx, pp2, pdinv, b2, (float4*)d_out, n, e);
}

// round 17
// speedup vs baseline: 1.3346x; 1.3346x over previous
#include <cuda_runtime.h>
#include <cuda_bf16.h>
#include <cstdint>
#include <cstddef>

// ---------------------------------------------------------------------------
// MultiModalClinicalGCN — round 16 passed (1017.8us, rel_err 1.6e-7).
// This round: GEMMs moved from FFMA (fp32 SIMT) to tensor pipe via
// mma.sync.m16n8k16.bf16 with 3-pass hi/lo split (fp32-grade accuracy):
//   C = Ah*Bh + Ah*Bl + Al*Bh,  x = hi(bf16) + lo(bf16 of residual)
// CSR-gather aggregation unchanged (proven).
// edge_index is int32 (JAX silently downcasts int64).
// ---------------------------------------------------------------------------

#define NMAX 100000
#define EMAX 1600000
#define TB 256
#define NB_MAX 512

#define ASTRIDE 40    // A smem row stride in bf16 (32 + 8 pad)
#define BSTRIDE 136   // B smem row stride in bf16 (128 + 8 pad)

__device__ float4 g_m   [(size_t)NMAX * 32];
__device__ float4 g_x1  [(size_t)NMAX * 32];
__device__ float4 g_p1  [(size_t)NMAX * 32];   // dinv[i]*h1[i]
__device__ float4 g_x2  [(size_t)NMAX * 32];
__device__ float4 g_p2  [NMAX];                // dinv[i]*h2[i]
__device__ float  g_dinv[NMAX];
__device__ int    g_cnt [NMAX];
__device__ int    g_off [NMAX + 1];
__device__ int    g_cur [NMAX];
__device__ int    g_bsum[NB_MAX];
__device__ int    g_boff[NB_MAX];
__device__ int    g_eidx[EMAX];

// ---------------- degree histogram ------------------------------------------
__global__ void k_zerocnt(int* cnt, int n) {
    int i = blockIdx.x * blockDim.x + threadIdx.x;
    if (i < n) cnt[i] = 0;
}

__global__ void k_hist(const int* __restrict__ dst, int* cnt, int n, int e) {
    int i = blockIdx.x * blockDim.x + threadIdx.x;
    if (i >= e) return;
    unsigned d = (unsigned)dst[i];
    if (d < (unsigned)n) atomicAdd(&cnt[d], 1);
}

// ---------------- hierarchical exclusive scan --------------------------------
__global__ void k_scan1(const int* __restrict__ cnt, int* __restrict__ off,
                        int* __restrict__ bsum, float* __restrict__ dinv, int n) {
    __shared__ int sh[TB];
    int tid = threadIdx.x;
    int i = blockIdx.x * TB + tid;
    int v = (i < n) ? cnt[i] : 0;
    if (i < n) dinv[i] = rsqrtf((float)v + 1.0f);
    sh[tid] = v;
    __syncthreads();
#pragma unroll
    for (int d = 1; d < TB; d <<= 1) {
        int t = (tid >= d) ? sh[tid - d] : 0;
        __syncthreads();
        sh[tid] += t;
        __syncthreads();
    }
    if (i < n) off[i] = sh[tid] - v;
    if (tid == TB - 1) bsum[blockIdx.x] = sh[TB - 1];
}

__global__ void k_scan2(const int* __restrict__ bsum, int* __restrict__ boff, int nb) {
    __shared__ int sh[NB_MAX];
    int tid = threadIdx.x;
    int v = (tid < nb) ? bsum[tid] : 0;
    sh[tid] = v;
    __syncthreads();
#pragma unroll
    for (int d = 1; d < NB_MAX; d <<= 1) {
        int t = (tid >= d) ? sh[tid - d] : 0;
        __syncthreads();
        sh[tid] += t;
        __syncthreads();
    }
    if (tid < nb) boff[tid] = sh[tid] - v;
}

__global__ void k_scan3(const int* __restrict__ cnt, const int* __restrict__ boff,
                        int* __restrict__ off, int* __restrict__ cur, int n) {
    int i = blockIdx.x * blockDim.x + threadIdx.x;
    if (i >= n) return;
    int o = off[i] + boff[i >> 8];
    off[i] = o;
    cur[i] = o;
    if (i == n - 1) off[n] = o + cnt[i];
}

__global__ void k_bucket(const int* __restrict__ src,
                         const int* __restrict__ dst,
                         int* cur, int* __restrict__ eidx, int n, int e) {
    int i = blockIdx.x * blockDim.x + threadIdx.x;
    if (i >= e) return;
    unsigned d = (unsigned)dst[i];
    if (d >= (unsigned)n) return;
    int p = atomicAdd(&cur[d], 1);
    if ((unsigned)p < (unsigned)e) eidx[p] = src[i];
}

// ---------------- mma helpers ------------------------------------------------
__device__ __forceinline__ void ldsm_x4(uint32_t& r0, uint32_t& r1,
                                        uint32_t& r2, uint32_t& r3, uint32_t a) {
    asm volatile("ldmatrix.sync.aligned.m8n8.x4.shared.b16 {%0,%1,%2,%3}, [%4];"
                 : "=r"(r0), "=r"(r1), "=r"(r2), "=r"(r3) : "r"(a));
}
__device__ __forceinline__ void ldsm_x4_t(uint32_t& r0, uint32_t& r1,
                                          uint32_t& r2, uint32_t& r3, uint32_t a) {
    asm volatile("ldmatrix.sync.aligned.m8n8.x4.trans.shared.b16 {%0,%1,%2,%3}, [%4];"
                 : "=r"(r0), "=r"(r1), "=r"(r2), "=r"(r3) : "r"(a));
}
__device__ __forceinline__ void mma_bf16(float* c, const uint32_t* a, const uint32_t* b) {
    asm volatile("mma.sync.aligned.m16n8k16.row.col.f32.bf16.bf16.f32 "
                 "{%0,%1,%2,%3},{%4,%5,%6,%7},{%8,%9},{%0,%1,%2,%3};"
                 : "+f"(c[0]), "+f"(c[1]), "+f"(c[2]), "+f"(c[3])
                 : "r"(a[0]), "r"(a[1]), "r"(a[2]), "r"(a[3]), "r"(b[0]), "r"(b[1]));
}

// ---------------- tensor-core GEMM, N fixed at 128 ---------------------------
// C[M,128] = A[M,K] * B[K,128]; A virtually = [A1 | A2] split at `split`.
// Split-bf16 3-pass for fp32-grade accuracy.
// Block 128x128, BK=32, 256 threads (8 warps, 4x2 grid, warp tile 32x64).
// EPI==0: C = relu(acc + bias[col]);  EPI==1: C = dinv[row]*acc
template <int EPI>
__global__ __launch_bounds__(256, 1)
void k_mma(const float* __restrict__ A1, int lda1,
           const float* __restrict__ A2, int lda2, int split,
           const float* __restrict__ B,
           const float* __restrict__ bias,
           const float* __restrict__ dinv,
           float* __restrict__ C, int M, int K) {
    __shared__ __nv_bfloat16 As_h[128 * ASTRIDE];
    __shared__ __nv_bfloat16 As_l[128 * ASTRIDE];
    __shared__ __nv_bfloat16 Bs_h[32 * BSTRIDE];
    __shared__ __nv_bfloat16 Bs_l[32 * BSTRIDE];

    const int tid  = threadIdx.x;
    const int lane = tid & 31;
    const int ww   = tid >> 5;
    const int wr = ww & 3, wc = ww >> 2;        // warp grid 4x2 -> tile 32x64
    const int rowBase = blockIdx.x * 128;

    float acc[2][8][4];
#pragma unroll
    for (int mt = 0; mt < 2; mt++)
#pragma unroll
        for (int nt = 0; nt < 8; nt++)
#pragma unroll
            for (int j = 0; j < 4; j++) acc[mt][nt][j] = 0.f;

    // ldmatrix source addresses (computed once, advanced by k-chunk inside loop)
    const int lj = lane >> 3, lr = lane & 7;
    // A: matrices (m0-7,k0-7),(m8-15,k0-7),(m0-7,k8-15),(m8-15,k8-15)
    const int a_row = wr * 32 + (lj & 1) * 8 + lr;     // + mt*16
    const int a_col = (lj >> 1) * 8;                   // + kc
    // B (trans): matrices (k0-7,n0-7),(k8-15,n0-7),(k0-7,n8-15),(k8-15,n8-15)
    const int b_row = (lj & 1) * 8 + lr;               // + kc
    const int b_col = wc * 64 + (lj >> 1) * 8;         // + np*16

    for (int k0 = 0; k0 < K; k0 += 32) {
        // ---- stage A tile 128x32 (fp32 -> bf16 hi/lo) ----
        const float* Ap; int lda, kcol;
        if (k0 < split) { Ap = A1; lda = lda1; kcol = k0; }
        else            { Ap = A2; lda = lda2; kcol = k0 - split; }
#pragma unroll
        for (int it = 0; it < 4; it++) {
            int fid = tid + it * 256;              // 0..1023 float4s
            int r   = fid >> 3;                    // 0..127
            int c4  = (fid & 7) * 4;               // 0..28
            int grow = rowBase + r;
            float4 v = make_float4(0.f, 0.f, 0.f, 0.f);
            if (grow < M)
                v = *reinterpret_cast<const float4*>(Ap + (size_t)grow * lda + kcol + c4);
            int o = r * ASTRIDE + c4;
            float xs[4] = {v.x, v.y, v.z, v.w};
#pragma unroll
            for (int j = 0; j < 4; j++) {
                __nv_bfloat16 h = __float2bfloat16(xs[j]);
                As_h[o + j] = h;
                As_l[o + j] = __float2bfloat16(xs[j] - __bfloat162float(h));
            }
        }
        // ---- stage B tile 32x128 ----
#pragma unroll
        for (int it = 0; it < 4; it++) {
            int fid = tid + it * 256;
            int kr  = fid >> 5;                    // 0..31
            int c4  = (fid & 31) * 4;              // 0..124
            float4 v = *reinterpret_cast<const float4*>(B + (size_t)(k0 + kr) * 128 + c4);
            int o = kr * BSTRIDE + c4;
            float xs[4] = {v.x, v.y, v.z, v.w};
#pragma unroll
            for (int j = 0; j < 4; j++) {
                __nv_bfloat16 h = __float2bfloat16(xs[j]);
                Bs_h[o + j] = h;
                Bs_l[o + j] = __float2bfloat16(xs[j] - __bfloat162float(h));
            }
        }
        __syncthreads();

        // ---- two k16 chunks ----
#pragma unroll
        for (int kc = 0; kc < 32; kc += 16) {
            uint32_t ah[2][4], al[2][4], bh[8][2], bl[8][2];
#pragma unroll
            for (int mt = 0; mt < 2; mt++) {
                int off = (a_row + mt * 16) * ASTRIDE + a_col + kc;
                uint32_t sh = (uint32_t)__cvta_generic_to_shared(&As_h[off]);
                uint32_t sl = (uint32_t)__cvta_generic_to_shared(&As_l[off]);
                ldsm_x4(ah[mt][0], ah[mt][1], ah[mt][2], ah[mt][3], sh);
                ldsm_x4(al[mt][0], al[mt][1], al[mt][2], al[mt][3], sl);
            }
#pragma unroll
            for (int np = 0; np < 4; np++) {
                int off = (b_row + kc) * BSTRIDE + b_col + np * 16;
                uint32_t sh = (uint32_t)__cvta_generic_to_shared(&Bs_h[off]);
                uint32_t sl = (uint32_t)__cvta_generic_to_shared(&Bs_l[off]);
                ldsm_x4_t(bh[np * 2][0], bh[np * 2][1], bh[np * 2 + 1][0], bh[np * 2 + 1][1], sh);
                ldsm_x4_t(bl[np * 2][0], bl[np * 2][1], bl[np * 2 + 1][0], bl[np * 2 + 1][1], sl);
            }
#pragma unroll
            for (int mt = 0; mt < 2; mt++)
#pragma unroll
                for (int nt = 0; nt < 8; nt++) {
                    mma_bf16(acc[mt][nt], ah[mt], bh[nt]);   // hi*hi
                    mma_bf16(acc[mt][nt], ah[mt], bl[nt]);   // hi*lo
                    mma_bf16(acc[mt][nt], al[mt], bh[nt]);   // lo*hi
                }
        }
        __syncthreads();
    }

    // ---- epilogue ----
    const int qr = lane >> 2, qc = (lane & 3) * 2;
#pragma unroll
    for (int mt = 0; mt < 2; mt++) {
#pragma unroll
        for (int half = 0; half < 2; half++) {
            int grow = rowBase + wr * 32 + mt * 16 + half * 8 + qr;
            if (grow >= M) continue;
            float scale = (EPI == 1) ? dinv[grow] : 1.f;
#pragma unroll
            for (int nt = 0; nt < 8; nt++) {
                int col = wc * 64 + nt * 8 + qc;
                float2 v;
                v.x = acc[mt][nt][half * 2 + 0];
                v.y = acc[mt][nt][half * 2 + 1];
                if (EPI == 0) {
                    float2 bb = *reinterpret_cast<const float2*>(bias + col);
                    v.x = fmaxf(v.x + bb.x, 0.f);
                    v.y = fmaxf(v.y + bb.y, 0.f);
                } else {
                    v.x *= scale; v.y *= scale;
                }
                *reinterpret_cast<float2*>(C + (size_t)grow * 128 + col) = v;
            }
        }
    }
}

// ---------------- conv1: warp-per-node gather + fused relu combine ----------
__global__ void k_gather1(const int* __restrict__ off,
                          const int* __restrict__ eidx,
                          const float4* __restrict__ p1,
                          const float* __restrict__ dinv,
                          const float* __restrict__ b1,
                          float4* __restrict__ x2, int n, int e) {
    int node = (blockIdx.x * blockDim.x + threadIdx.x) >> 5;
    if (node >= n) return;
    int lane = threadIdx.x & 31;
    int beg = off[node], end = off[node + 1];
    beg = min(max(beg, 0), e);
    end = min(max(end, beg), e);

    float4 acc = p1[(size_t)node * 32 + lane];   // self-loop term

    for (int t = beg; t < end; t++) {
        unsigned s = (unsigned)eidx[t];
        if (s >= (unsigned)n) continue;
        float4 v = __ldg(p1 + (size_t)s * 32 + lane);
        acc.x += v.x; acc.y += v.y; acc.z += v.z; acc.w += v.w;
    }

    float s = dinv[node];
    float4 bb = *reinterpret_cast<const float4*>(b1 + lane * 4);
    float4 r;
    r.x = fmaxf(fmaf(s, acc.x, bb.x), 0.f);
    r.y = fmaxf(fmaf(s, acc.y, bb.y), 0.f);
    r.z = fmaxf(fmaf(s, acc.z, bb.z), 0.f);
    r.w = fmaxf(fmaf(s, acc.w, bb.w), 0.f);
    x2[(size_t)node * 32 + lane] = r;
}

// ---------------- p2 = dinv * (x2 @ W2[128,4]), one warp per node -----------
__global__ void k_gemm4(const float4* __restrict__ x2,
                        const float* __restrict__ W2,
                        const float* __restrict__ dinv,
                        float4* __restrict__ p2, int n) {
    int gw = (blockIdx.x * blockDim.x + threadIdx.x) >> 5;
    if (gw >= n) return;
    int lane = threadIdx.x & 31;
    float4 x = x2[(size_t)gw * 32 + lane];
    const float4* W = reinterpret_cast<const float4*>(W2) + lane * 4;
    float4 w0 = W[0], w1 = W[1], w2 = W[2], w3 = W[3];
    float4 acc;
    acc.x = x.x * w0.x + x.y * w1.x + x.z * w2.x + x.w * w3.x;
    acc.y = x.x * w0.y + x.y * w1.y + x.z * w2.y + x.w * w3.y;
    acc.z = x.x * w0.z + x.y * w1.z + x.z * w2.z + x.w * w3.z;
    acc.w = x.x * w0.w + x.y * w1.w + x.z * w2.w + x.w * w3.w;
#pragma unroll
    for (int o = 16; o > 0; o >>= 1) {
        acc.x += __shfl_xor_sync(0xffffffffu, acc.x, o);
        acc.y += __shfl_xor_sync(0xffffffffu, acc.y, o);
        acc.z += __shfl_xor_sync(0xffffffffu, acc.z, o);
        acc.w += __shfl_xor_sync(0xffffffffu, acc.w, o);
    }
    if (lane == 0) {
        float s = dinv[gw];
        p2[gw] = make_float4(s * acc.x, s * acc.y, s * acc.z, s * acc.w);
    }
}

// ---------------- conv2: warp-per-node lane-strided gather ------------------
__global__ void k_gather2(const int* __restrict__ off,
                          const int* __restrict__ eidx,
                          const float4* __restrict__ p2,
                          const float* __restrict__ dinv,
                          const float* __restrict__ b2,
                          float4* __restrict__ out, int n, int e) {
    int node = (blockIdx.x * blockDim.x + threadIdx.x) >> 5;
    if (node >= n) return;
    int lane = threadIdx.x & 31;
    int beg = off[node], end = off[node + 1];
    beg = min(max(beg, 0), e);
    end = min(max(end, beg), e);

    float4 acc = make_float4(0.f, 0.f, 0.f, 0.f);
    for (int t = beg + lane; t < end; t += 32) {
        unsigned s = (unsigned)eidx[t];
        if (s >= (unsigned)n) continue;
        float4 v = __ldg(p2 + s);
        acc.x += v.x; acc.y += v.y; acc.z += v.z; acc.w += v.w;
    }
#pragma unroll
    for (int o = 16; o > 0; o >>= 1) {
        acc.x += __shfl_xor_sync(0xffffffffu, acc.x, o);
        acc.y += __shfl_xor_sync(0xffffffffu, acc.y, o);
        acc.z += __shfl_xor_sync(0xffffffffu, acc.z, o);
        acc.w += __shfl_xor_sync(0xffffffffu, acc.w, o);
    }
    if (lane == 0) {
        float s  = dinv[node];
        float4 p = p2[node];
        float4 b = *reinterpret_cast<const float4*>(b2);
        float4 o;
        o.x = fmaf(s, acc.x + p.x, b.x);
        o.y = fmaf(s, acc.y + p.y, b.y);
        o.z = fmaf(s, acc.z + p.z, b.z);
        o.w = fmaf(s, acc.w + p.w, b.w);
        out[node] = o;
    }
}

// ---------------------------------------------------------------------------
extern "C" void kernel_launch(void* const* d_in, const int* in_sizes, int n_in,
                              void* d_out, int out_size) {
    const float* clinical = (const float*)d_in[0];
    const float* mel      = (const float*)d_in[1];
    const int*   ei       = (const int*)d_in[2];     // int32 (JAX x64 disabled)
    const float* W_mel    = (const float*)d_in[3];
    const float* b_mel    = (const float*)d_in[4];
    const float* W_cat    = (const float*)d_in[5];
    const float* b_cat    = (const float*)d_in[6];
    const float* W1       = (const float*)d_in[7];
    const float* b1       = (const float*)d_in[8];
    const float* W2       = (const float*)d_in[9];
    const float* b2       = (const float*)d_in[10];

    int n = in_sizes[0] / 64;        // 100000
    int e = in_sizes[2] / 2;         // 1600000
    if (n > NMAX) n = NMAX;
    if (e > EMAX) e = EMAX;
    const int* src = ei;
    const int* dst = ei + e;

    float4 *pm, *px1, *pp1, *px2, *pp2;
    float  *pdinv;
    int    *pcnt, *poff, *pcur, *peidx, *pbsum, *pboff;
    cudaGetSymbolAddress((void**)&pm,    g_m);
    cudaGetSymbolAddress((void**)&px1,   g_x1);
    cudaGetSymbolAddress((void**)&pp1,   g_p1);
    cudaGetSymbolAddress((void**)&px2,   g_x2);
    cudaGetSymbolAddress((void**)&pp2,   g_p2);
    cudaGetSymbolAddress((void**)&pdinv, g_dinv);
    cudaGetSymbolAddress((void**)&pcnt,  g_cnt);
    cudaGetSymbolAddress((void**)&poff,  g_off);
    cudaGetSymbolAddress((void**)&pcur,  g_cur);
    cudaGetSymbolAddress((void**)&peidx, g_eidx);
    cudaGetSymbolAddress((void**)&pbsum, g_bsum);
    cudaGetSymbolAddress((void**)&pboff, g_boff);

    int gn = (n + TB - 1) / TB;
    int ge = (e + TB - 1) / TB;

    // --- CSR build (bucket edges by dst) + dinv
    k_zerocnt<<<gn, TB>>>(pcnt, n);
    k_hist<<<ge, TB>>>(dst, pcnt, n, e);
    k_scan1<<<gn, TB>>>(pcnt, poff, pbsum, pdinv, n);
    k_scan2<<<1, NB_MAX>>>(pbsum, pboff, gn);
    k_scan3<<<gn, TB>>>(pcnt, pboff, poff, pcur, n);
    k_bucket<<<ge, TB>>>(src, dst, pcur, peidx, n, e);

    // --- dense pipeline (tensor cores, split-bf16 3-pass)
    int gm = (n + 127) / 128;
    // m = relu(mel @ W_mel + b_mel)
    k_mma<0><<<gm, 256>>>(mel, 1024, nullptr, 0, 1 << 30,
                          W_mel, b_mel, nullptr, (float*)pm, n, 1024);
    // x1 = relu([clinical | m] @ W_cat + b_cat)   (virtual concat, split=64)
    k_mma<0><<<gm, 256>>>(clinical, 64, (const float*)pm, 128, 64,
                          W_cat, b_cat, nullptr, (float*)px1, n, 192);
    // p1 = dinv * (x1 @ W1)
    k_mma<1><<<gm, 256>>>((const float*)px1, 128, nullptr, 0, 1 << 30,
                          W1, nullptr, pdinv, (float*)pp1, n, 128);

    // conv1 gather + fused relu combine -> x2
    int gw = (n * 32 + TB - 1) / TB;   // one warp per node
    k_gather1<<<gw, TB>>>(poff, peidx, pp1, pdinv, b1, px2, n, e);

    // p2 = dinv * (x2 @ W2)
    k_gemm4<<<gw, TB>>>(px2, W2, pdinv, pp2, n);

    // conv2 gather -> out
    k_gather2<<<gw, TB>>>(poff, peidx, pp2, pdinv, b2, (float4*)d_out, n, e);
}